// round 4
// baseline (speedup 1.0000x reference)
#include <cuda_runtime.h>
#include <cstdint>

// RWKV7 chunked attention, B=4 T=2048 H=32 C=64 dT=16.
// One CTA (512 thr) per (b,h); warp-specialized intervals + f32x2 packed FMA.

#define B_ 4
#define T_ 2048
#define H_ 32
#define C_ 64
#define DT_ 16
#define NT_ (T_ / DT_)
#define THREADS 512

typedef unsigned long long u64;

// ---- shared layout (float words) ----
#define OFF_WQ   0
#define OFF_WA   1024
#define OFF_KWI  2048
#define OFF_BWI  3072
#define OFF_V    4096
#define OFF_U    5120
#define OFF_ABU  6144
#define OFF_AB   7168     // [16][16] masked
#define OFF_QB   7424     // [16][16] masked
#define OFF_AKQK 7680     // [16][16] float2 (ak,qk) masked
#define OFF_LP   8192     // [8][64]
#define OFF_FW   8704     // [64]
#define OFF_ST   8768     // [64][64] swizzled
#define SMEM_WORDS (OFF_ST + 4096)
#define SMEM_BYTES (SMEM_WORDS * 4)

// xor swizzle: tiles [16][64]: float4-group f stored at f^row; st [64][64]: f^(row>>2)
__device__ __forceinline__ int tile_off(int row, int f) {       // float4-aligned word offset
    return row * 64 + (((f ^ row) & 15) << 2);
}
__device__ __forceinline__ int tile_w(int row, int c) {         // scalar word offset
    return row * 64 + ((((c >> 2) ^ row) & 15) << 2) + (c & 3);
}
__device__ __forceinline__ int st_off(int row, int f) {
    return row * 64 + (((f ^ (row >> 2)) & 15) << 2);
}

__device__ __forceinline__ float4 ld4(const float* p) { return *reinterpret_cast<const float4*>(p); }
__device__ __forceinline__ void st4(float* p, float4 v) { *reinterpret_cast<float4*>(p) = v; }
__device__ __forceinline__ ulonglong2 ldp(const float* p) { return *reinterpret_cast<const ulonglong2*>(p); }
__device__ __forceinline__ void stp(float* p, ulonglong2 v) { *reinterpret_cast<ulonglong2*>(p) = v; }

__device__ __forceinline__ u64 pk2(float lo, float hi) {
    u64 r; asm("mov.b64 %0, {%1, %2};" : "=l"(r) : "f"(lo), "f"(hi)); return r;
}
__device__ __forceinline__ void un2(u64 v, float& lo, float& hi) {
    asm("mov.b64 {%0, %1}, %2;" : "=f"(lo), "=f"(hi) : "l"(v));
}
__device__ __forceinline__ void fma2(u64& d, u64 a, u64 b) {
    asm("fma.rn.f32x2 %0, %1, %2, %0;" : "+l"(d) : "l"(a), "l"(b));
}
__device__ __forceinline__ u64 add2(u64 a, u64 b) {
    u64 d; asm("add.rn.f32x2 %0, %1, %2;" : "=l"(d) : "l"(a), "l"(b)); return d;
}
__device__ __forceinline__ u64 mul2(u64 a, u64 b) {
    u64 d; asm("mul.rn.f32x2 %0, %1, %2;" : "=l"(d) : "l"(a), "l"(b)); return d;
}

__global__ __launch_bounds__(THREADS, 1)
void rwkv7_kernel(const float* __restrict__ gw, const float* __restrict__ gq,
                  const float* __restrict__ gk, const float* __restrict__ gv,
                  const float* __restrict__ ga, const float* __restrict__ gb,
                  const float* __restrict__ gs0, float* __restrict__ gy)
{
    extern __shared__ float sm[];

    const int bh  = blockIdx.x;
    const int b   = bh / H_;
    const int h   = bh % H_;
    const int tid = threadIdx.x;

    // loader mapping: 8 t-pairs x 64 columns
    const int t2 = tid >> 6;       // 0..7, owns t = 2*t2, 2*t2+1
    const int cl = tid & 63;

    // X-group mapping (tid<256): warp w: 4 t's x 8 i-quads
    const int w    = tid >> 5;
    const int ihx  = (w >> 2) & 1;
    const int tbx  = (w & 3) * 4;
    const int tx   = tbx + ((tid >> 3) & 3);     // t for X thread
    const int iqx  = ihx * 8 + (tid & 7);        // i-quad 0..15
    // Y-group mapping (tid>=256): g = tid-256: (tg = g>>4, sg = g&15)
    const int g    = tid & 255;
    const int tgy  = g >> 4;
    const int sgy  = g & 15;

    // ---- init state ----
    {
        const float* s0p = gs0 + (size_t)bh * C_ * C_;
        #pragma unroll
        for (int q4 = tid; q4 < 1024; q4 += THREADS) {
            int row = q4 >> 4, f = q4 & 15;
            st4(sm + OFF_ST + st_off(row, f), ld4(s0p + row * 64 + f * 4));
        }
    }

    const size_t stride_t = (size_t)H_ * C_;

    // prefetch chunk 0
    float rw[2], rq[2], rk[2], rv[2], ra[2], rb[2];
    {
        size_t base = (((size_t)b * T_ + 2 * t2) * H_ + h) * C_ + cl;
        #pragma unroll
        for (int r = 0; r < 2; r++) {
            size_t ix = base + (size_t)r * stride_t;
            rw[r] = gw[ix]; rq[r] = gq[ix]; rk[r] = gk[ix];
            rv[r] = gv[ix]; ra[r] = ga[ix]; rb[r] = gb[ix];
        }
    }
    __syncthreads();

    for (int ch = 0; ch < NT_; ch++) {
        const int t0 = ch * DT_;

        // ===== A: local decay products =====
        float wd[2];
        {
            wd[0] = __expf(-__expf(rw[0]));
            wd[1] = __expf(-__expf(rw[1]));
            sm[OFF_LP + t2 * 64 + cl] = wd[0] * wd[1];
        }
        __syncthreads();

        // ===== B: prefix, scale, stage tiles; prefetch next =====
        {
            float pre = 1.0f;
            #pragma unroll
            for (int gg = 0; gg < 7; gg++)
                if (gg < t2) pre *= sm[OFF_LP + gg * 64 + cl];
            float incl = pre;
            #pragma unroll
            for (int r = 0; r < 2; r++) {
                int t = 2 * t2 + r;
                float ip = incl;
                incl *= wd[r];
                float rinv = __fdividef(1.0f, incl);
                int tw = tile_w(t, cl);
                sm[OFF_WQ  + tw] = rq[r] * incl;
                sm[OFF_WA  + tw] = ra[r] * ip;
                sm[OFF_KWI + tw] = rk[r] * rinv;
                sm[OFF_BWI + tw] = rb[r] * rinv;
                sm[OFF_V   + tw] = rv[r];
            }
            if (t2 == 7) sm[OFF_FW + cl] = incl;
        }
        if (ch + 1 < NT_) {
            size_t base = (((size_t)b * T_ + (t0 + DT_) + 2 * t2) * H_ + h) * C_ + cl;
            #pragma unroll
            for (int r = 0; r < 2; r++) {
                size_t ix = base + (size_t)r * stride_t;
                rw[r] = gw[ix]; rq[r] = gq[ix]; rk[r] = gk[ix];
                rv[r] = gv[ix]; ra[r] = ga[ix]; rb[r] = gb[ix];
            }
        }
        __syncthreads();

        // persistent across intervals
        float yp[4];                 // X: y partials
        u64  ayp[4];                 // X: (abu, yp) packed accumulators
        u64  accY[4][2];             // Y: state-update accumulators

        // ===== interval 3: X = state GEMM, Y = grams =====
        if (tid < 256) {
            u64 aa2[4] = {0,0,0,0}, ay2[4] = {0,0,0,0};
            #pragma unroll
            for (int j4 = 0; j4 < 16; j4++) {
                int tf = ((j4 ^ tx) & 15) << 2;
                ulonglong2 A = ldp(sm + OFF_WA + tx * 64 + tf);
                ulonglong2 Q = ldp(sm + OFF_WQ + tx * 64 + tf);
                int sf = ((j4 ^ iqx) & 15) << 2;
                #pragma unroll
                for (int r = 0; r < 4; r++) {
                    ulonglong2 S = ldp(sm + OFF_ST + (4 * iqx + r) * 64 + sf);
                    fma2(aa2[r], A.x, S.x); fma2(aa2[r], A.y, S.y);
                    fma2(ay2[r], Q.x, S.x); fma2(ay2[r], Q.y, S.y);
                }
            }
            #pragma unroll
            for (int r = 0; r < 4; r++) {
                float l0, h0, l1, h1;
                un2(aa2[r], l0, h0); un2(ay2[r], l1, h1);
                ayp[r] = pk2(l0 + h0, l1 + h1);
            }
        } else {
            // Y: grams (tg = tgy, sg = sgy)
            u64 ab2 = 0, ak2 = 0, qb2 = 0, qk2 = 0;
            #pragma unroll
            for (int c4 = 0; c4 < 16; c4++) {
                int ftg = ((c4 ^ tgy) & 15) << 2;
                int fsg = ((c4 ^ sgy) & 15) << 2;
                ulonglong2 A  = ldp(sm + OFF_WA  + tgy * 64 + ftg);
                ulonglong2 Q  = ldp(sm + OFF_WQ  + tgy * 64 + ftg);
                ulonglong2 Bv = ldp(sm + OFF_BWI + sgy * 64 + fsg);
                ulonglong2 Kv = ldp(sm + OFF_KWI + sgy * 64 + fsg);
                fma2(ab2, A.x, Bv.x); fma2(ab2, A.y, Bv.y);
                fma2(ak2, A.x, Kv.x); fma2(ak2, A.y, Kv.y);
                fma2(qb2, Q.x, Bv.x); fma2(qb2, Q.y, Bv.y);
                fma2(qk2, Q.x, Kv.x); fma2(qk2, Q.y, Kv.y);
            }
            float l, hi2, ab, ak, qb, qk;
            un2(ab2, l, hi2); ab = l + hi2;
            un2(ak2, l, hi2); ak = l + hi2;
            un2(qb2, l, hi2); qb = l + hi2;
            un2(qk2, l, hi2); qk = l + hi2;
            float mstr = (tgy > sgy)  ? 1.f : 0.f;
            float minc = (tgy >= sgy) ? 1.f : 0.f;
            sm[OFF_AB + tgy * 16 + sgy] = ab * mstr;
            sm[OFF_QB + tgy * 16 + sgy] = qb * minc;
            *reinterpret_cast<u64*>(sm + OFF_AKQK + (tgy * 16 + sgy) * 2) =
                pk2(ak * mstr, qk * minc);
        }
        __syncthreads();   // bar3: grams ready

        // ===== interval 4: X = (ak,qk)@v -> abu; Y = accv = v^T kwi =====
        if (tid < 256) {
            #pragma unroll
            for (int s2 = 0; s2 < 8; s2++) {
                ulonglong2 ak2 = ldp(sm + OFF_AKQK + tx * 32 + s2 * 4);
                float4 v4a = ld4(sm + OFF_V + tile_off(2 * s2,     iqx));
                float4 v4b = ld4(sm + OFF_V + tile_off(2 * s2 + 1, iqx));
                fma2(ayp[0], ak2.x, pk2(v4a.x, v4a.x));
                fma2(ayp[1], ak2.x, pk2(v4a.y, v4a.y));
                fma2(ayp[2], ak2.x, pk2(v4a.z, v4a.z));
                fma2(ayp[3], ak2.x, pk2(v4a.w, v4a.w));
                fma2(ayp[0], ak2.y, pk2(v4b.x, v4b.x));
                fma2(ayp[1], ak2.y, pk2(v4b.y, v4b.y));
                fma2(ayp[2], ak2.y, pk2(v4b.z, v4b.z));
                fma2(ayp[3], ak2.y, pk2(v4b.w, v4b.w));
            }
            float abu[4];
            #pragma unroll
            for (int r = 0; r < 4; r++) un2(ayp[r], abu[r], yp[r]);
            st4(sm + OFF_ABU + tile_off(tx, iqx),
                make_float4(abu[0], abu[1], abu[2], abu[3]));
        } else {
            #pragma unroll
            for (int r = 0; r < 4; r++) { accY[r][0] = 0; accY[r][1] = 0; }
            #pragma unroll
            for (int t = 0; t < DT_; t++) {
                float4 v4 = ld4(sm + OFF_V + tile_off(t, tgy));
                ulonglong2 K2 = ldp(sm + OFF_KWI + t * 64 + (((sgy ^ t) & 15) << 2));
                u64 v0 = pk2(v4.x, v4.x), v1 = pk2(v4.y, v4.y);
                u64 v2 = pk2(v4.z, v4.z), v3 = pk2(v4.w, v4.w);
                fma2(accY[0][0], v0, K2.x); fma2(accY[0][1], v0, K2.y);
                fma2(accY[1][0], v1, K2.x); fma2(accY[1][1], v1, K2.y);
                fma2(accY[2][0], v2, K2.x); fma2(accY[2][1], v2, K2.y);
                fma2(accY[3][0], v3, K2.x); fma2(accY[3][1], v3, K2.y);
            }
        }
        __syncthreads();       // bar4: abu + ab complete

        // ===== interval 5: solve (I-ab) u = abu, threads 0..63, 4-acc ILP =====
        if (tid < 64) {
            const int c = tid;
            float uu[DT_];
            #pragma unroll
            for (int t = 0; t < DT_; t++)
                uu[t] = sm[OFF_ABU + tile_w(t, c)];
            #pragma unroll
            for (int t = 1; t < DT_; t++) {
                float acc0 = uu[t], acc1 = 0.f, acc2 = 0.f, acc3 = 0.f;
                const float* abr = sm + OFF_AB + t * 16;
                #pragma unroll
                for (int s4 = 0; 4 * s4 < t; s4++) {
                    float4 abq = ld4(abr + 4 * s4);
                    int s = 4 * s4;
                    if (s     < t) acc0 += abq.x * uu[s];
                    if (s + 1 < t) acc1 += abq.y * uu[s + 1];
                    if (s + 2 < t) acc2 += abq.z * uu[s + 2];
                    if (s + 3 < t) acc3 += abq.w * uu[s + 3];
                }
                uu[t] = (acc0 + acc1) + (acc2 + acc3);
            }
            #pragma unroll
            for (int t = 0; t < DT_; t++)
                sm[OFF_U + tile_w(t, c)] = uu[t];
        }
        __syncthreads();       // bar5: u ready

        // ===== interval 6 =====
        if (tid < 256) {
            // X: y = yp + qb@u, store to gmem (streaming)
            float4 qbr[4];
            #pragma unroll
            for (int r = 0; r < 4; r++) qbr[r] = ld4(sm + OFF_QB + tx * 16 + 4 * r);
            u64 y01 = pk2(yp[0], yp[1]);
            u64 y23 = pk2(yp[2], yp[3]);
            #pragma unroll
            for (int s = 0; s < 16; s++) {
                float qbs = (s & 2) ? ((s & 1) ? qbr[s >> 2].w : qbr[s >> 2].z)
                                    : ((s & 1) ? qbr[s >> 2].y : qbr[s >> 2].x);
                ulonglong2 U2 = ldp(sm + OFF_U + tile_off(s, iqx));
                u64 q2 = pk2(qbs, qbs);
                fma2(y01, q2, U2.x);
                fma2(y23, q2, U2.y);
            }
            float o0, o1, o2, o3;
            un2(y01, o0, o1); un2(y23, o2, o3);
            size_t yb = (((size_t)b * T_ + t0 + tx) * H_ + h) * C_ + 4 * iqx;
            __stcs(reinterpret_cast<float4*>(gy + yb), make_float4(o0, o1, o2, o3));
        } else {
            // Y: accu += u^T bwi ; st = (st + acc) * fw
            #pragma unroll
            for (int t = 0; t < DT_; t++) {
                float4 u4 = ld4(sm + OFF_U + tile_off(t, tgy));
                ulonglong2 B2 = ldp(sm + OFF_BWI + t * 64 + (((sgy ^ t) & 15) << 2));
                u64 u0 = pk2(u4.x, u4.x), u1 = pk2(u4.y, u4.y);
                u64 u2 = pk2(u4.z, u4.z), u3 = pk2(u4.w, u4.w);
                fma2(accY[0][0], u0, B2.x); fma2(accY[0][1], u0, B2.y);
                fma2(accY[1][0], u1, B2.x); fma2(accY[1][1], u1, B2.y);
                fma2(accY[2][0], u2, B2.x); fma2(accY[2][1], u2, B2.y);
                fma2(accY[3][0], u3, B2.x); fma2(accY[3][1], u3, B2.y);
            }
            ulonglong2 FWp = ldp(sm + OFF_FW + 4 * sgy);
            #pragma unroll
            for (int r = 0; r < 4; r++) {
                float* sp = sm + OFF_ST + (4 * tgy + r) * 64 + (((sgy ^ tgy) & 15) << 2);
                ulonglong2 S = ldp(sp);
                ulonglong2 Sn;
                Sn.x = mul2(add2(S.x, accY[r][0]), FWp.x);
                Sn.y = mul2(add2(S.y, accY[r][1]), FWp.y);
                stp(sp, Sn);
            }
        }
        __syncthreads();       // bar6: st updated
    }
}

extern "C" void kernel_launch(void* const* d_in, const int* in_sizes, int n_in,
                              void* d_out, int out_size)
{
    const float* w  = (const float*)d_in[0];
    const float* q  = (const float*)d_in[1];
    const float* k  = (const float*)d_in[2];
    const float* v  = (const float*)d_in[3];
    const float* a  = (const float*)d_in[4];
    const float* b  = (const float*)d_in[5];
    const float* s0 = (const float*)d_in[6];
    float* y = (float*)d_out;

    cudaFuncSetAttribute(rwkv7_kernel, cudaFuncAttributeMaxDynamicSharedMemorySize, SMEM_BYTES);
    rwkv7_kernel<<<B_ * H_, THREADS, SMEM_BYTES>>>(w, q, k, v, a, b, s0, y);
}